// round 2
// baseline (speedup 1.0000x reference)
#include <cuda_runtime.h>
#include <cuda_bf16.h>

// HDConvEncoder: 8-step depthwise-conv3 recurrence + LayerNorm(L) + pw scale/bias + exact GELU + residual.
// B=32, C=256, L=4096, S=8, Cs=32.
// One block per (b, c_local) chain: B*Cs = 1024 blocks. y-state lives in registers
// (recurrence is elementwise in l across groups); only z needs SMEM for the +/-1 conv taps.

#define NTHREADS 512
#define LLEN 4096
#define NGROUPS 8
#define CS 32
#define CTOT 256

__device__ __forceinline__ float gelu_ln(float y, float mean, float rstd,
                                         float g, float be, float pww, float pwb) {
    float n = (y - mean) * rstd * g + be;
    float t = n * pww + pwb;
    return 0.5f * t * (1.0f + erff(t * 0.70710678118654752440f));
}

__global__ void __launch_bounds__(NTHREADS, 2)
hdconv_encoder_kernel(const float* __restrict__ x,
                      const float* __restrict__ conv_w,   // [8,3,32]
                      const float* __restrict__ conv_b,   // [8,32]
                      const float* __restrict__ ln_g,     // [4096]
                      const float* __restrict__ ln_b,     // [4096]
                      const float* __restrict__ pw_w,     // [256]
                      const float* __restrict__ pw_b,     // [256]
                      float* __restrict__ out)
{
    extern __shared__ float sm[];
    float* sgam = sm;              // 4096
    float* sbet = sm + LLEN;       // 4096
    float* zbuf = sm + 2 * LLEN;   // 4096
    float* red  = sm + 3 * LLEN;   // 32*2 partials + 2 stats

    const int tid  = threadIdx.x;
    const int b    = blockIdx.x >> 5;   // / CS
    const int cl   = blockIdx.x & 31;   // c_local

    // Load gamma/beta into SMEM (reused 8x).
    {
        const float4* g4 = (const float4*)ln_g;
        const float4* b4 = (const float4*)ln_b;
        float4* sg4 = (float4*)sgam;
        float4* sb4 = (float4*)sbet;
#pragma unroll
        for (int j = 0; j < 2; j++) {
            int q = tid + j * NTHREADS;
            sg4[q] = g4[q];
            sb4[q] = b4[q];
        }
    }

    const float* xbase = x   + ((long)b * CTOT + cl) * LLEN; // group-0 row of this chain
    float*       obase = out + ((long)b * CTOT + cl) * LLEN;

    float4 yv[2];
    yv[0] = make_float4(0.f, 0.f, 0.f, 0.f);
    yv[1] = make_float4(0.f, 0.f, 0.f, 0.f);

    // Preload x for group 0 (streaming: read-once data).
    float4 xv[2];
    {
        const float4* xr = (const float4*)xbase;
        xv[0] = __ldcs(xr + tid);
        xv[1] = __ldcs(xr + tid + NTHREADS);
    }

    __syncthreads(); // gamma/beta visible

#pragma unroll 1
    for (int i = 0; i < NGROUPS; i++) {
        // Prefetch next group's x row early to hide DRAM latency.
        float4 xn[2];
        if (i < NGROUPS - 1) {
            const float4* xr = (const float4*)(xbase + (long)(i + 1) * CS * LLEN);
            xn[0] = __ldcs(xr + tid);
            xn[1] = __ldcs(xr + tid + NTHREADS);
        }

        // Per-group scalars (broadcast loads, L2-resident).
        const float w0  = __ldg(conv_w + i * 96 + 0 * 32 + cl);
        const float w1  = __ldg(conv_w + i * 96 + 1 * 32 + cl);
        const float w2  = __ldg(conv_w + i * 96 + 2 * 32 + cl);
        const float bb  = __ldg(conv_b + i * 32 + cl);
        const float pww = __ldg(pw_w + i * 32 + cl);
        const float pwb = __ldg(pw_b + i * 32 + cl);

        // z = x + y_prev  (elementwise, same-thread indices) -> SMEM for conv taps.
        float4* z4 = (float4*)zbuf;
#pragma unroll
        for (int j = 0; j < 2; j++) {
            float4 z;
            z.x = xv[j].x + yv[j].x;
            z.y = xv[j].y + yv[j].y;
            z.z = xv[j].z + yv[j].z;
            z.w = xv[j].w + yv[j].w;
            z4[tid + j * NTHREADS] = z;
        }
        __syncthreads(); // z visible to neighbor threads

        // Depthwise conv3 with zero padding; overwrite yv with y_i; accumulate LN partials.
        float s = 0.f, ss = 0.f;
#pragma unroll
        for (int j = 0; j < 2; j++) {
            int q  = tid + j * NTHREADS;
            int l0 = q << 2;
            float4 zc = z4[q];
            float zm = (l0 > 0)          ? zbuf[l0 - 1] : 0.f;
            float zp = (l0 + 4 < LLEN)   ? zbuf[l0 + 4] : 0.f;
            float4 yo;
            yo.x = fmaf(w0, zm,   fmaf(w1, zc.x, fmaf(w2, zc.y, bb)));
            yo.y = fmaf(w0, zc.x, fmaf(w1, zc.y, fmaf(w2, zc.z, bb)));
            yo.z = fmaf(w0, zc.y, fmaf(w1, zc.z, fmaf(w2, zc.w, bb)));
            yo.w = fmaf(w0, zc.z, fmaf(w1, zc.w, fmaf(w2, zp,   bb)));
            s  += yo.x + yo.y + yo.z + yo.w;
            ss += yo.x * yo.x + yo.y * yo.y + yo.z * yo.z + yo.w * yo.w;
            yv[j] = yo;
        }

        // Block reduction of (s, ss). Its first __syncthreads also fences zbuf
        // (all conv reads done) against next iteration's z writes.
#pragma unroll
        for (int o = 16; o > 0; o >>= 1) {
            s  += __shfl_xor_sync(0xFFFFFFFFu, s,  o);
            ss += __shfl_xor_sync(0xFFFFFFFFu, ss, o);
        }
        const int warp = tid >> 5, lane = tid & 31;
        if (lane == 0) { red[warp * 2] = s; red[warp * 2 + 1] = ss; }
        __syncthreads();
        if (warp == 0) {
            float a = (lane < 16) ? red[lane * 2]     : 0.f;
            float c = (lane < 16) ? red[lane * 2 + 1] : 0.f;
#pragma unroll
            for (int o = 8; o > 0; o >>= 1) {
                a += __shfl_xor_sync(0xFFFFFFFFu, a, o);
                c += __shfl_xor_sync(0xFFFFFFFFu, c, o);
            }
            if (lane == 0) {
                float mean = a * (1.0f / (float)LLEN);
                float var  = c * (1.0f / (float)LLEN) - mean * mean;
                red[64] = mean;
                red[65] = rsqrtf(var + 1e-6f);
            }
        }
        __syncthreads();
        const float mean = red[64];
        const float rstd = red[65];

        // LN + pw + exact gelu + residual; streaming store.
        float4* orow = (float4*)(obase + (long)i * CS * LLEN);
#pragma unroll
        for (int j = 0; j < 2; j++) {
            int q = tid + j * NTHREADS;
            float4 yo = yv[j];
            float4 xo = xv[j];
            float4 g  = ((const float4*)sgam)[q];
            float4 be = ((const float4*)sbet)[q];
            float4 o;
            o.x = xo.x + gelu_ln(yo.x, mean, rstd, g.x, be.x, pww, pwb);
            o.y = xo.y + gelu_ln(yo.y, mean, rstd, g.y, be.y, pww, pwb);
            o.z = xo.z + gelu_ln(yo.z, mean, rstd, g.z, be.z, pww, pwb);
            o.w = xo.w + gelu_ln(yo.w, mean, rstd, g.w, be.w, pww, pwb);
            __stcs(orow + q, o);
        }

        // Rotate prefetched x in.
        if (i < NGROUPS - 1) { xv[0] = xn[0]; xv[1] = xn[1]; }
    }
}

extern "C" void kernel_launch(void* const* d_in, const int* in_sizes, int n_in,
                              void* d_out, int out_size)
{
    const float* x      = (const float*)d_in[0];
    const float* conv_w = (const float*)d_in[1];
    const float* conv_b = (const float*)d_in[2];
    const float* ln_g   = (const float*)d_in[3];
    const float* ln_b   = (const float*)d_in[4];
    const float* pw_w   = (const float*)d_in[5];
    const float* pw_b   = (const float*)d_in[6];
    float* out = (float*)d_out;

    const int smem_bytes = (3 * LLEN + 66) * (int)sizeof(float); // 49416
    cudaFuncSetAttribute(hdconv_encoder_kernel,
                         cudaFuncAttributeMaxDynamicSharedMemorySize, smem_bytes);

    dim3 grid(32 * 32); // B * Cs = 1024 chains
    dim3 block(NTHREADS);
    hdconv_encoder_kernel<<<grid, block, smem_bytes>>>(
        x, conv_w, conv_b, ln_g, ln_b, pw_w, pw_b, out);
}